// round 17
// baseline (speedup 1.0000x reference)
#include <cuda_runtime.h>
#include <cuda_fp16.h>
#include <cstdint>
#include <math.h>

// -------- problem shape --------
#define BHN    64
#define MSEQ   1024
#define DIMN   64
#define LSPAN  1024
#define KVROWS (MSEQ + LSPAN)
#define BM     64
#define BL     128
#define NT     (LSPAN / BL)
#define NTHR   512

// -------- fp16 preconverted operands (device scratch; allocation-free) --------
__device__ __half g_Qh [(size_t)BHN * MSEQ  * DIMN];   //  8 MB, [bh][i][d]  (pre-scaled x0.125)
__device__ __half g_Kh [(size_t)BHN * KVROWS * DIMN];  // 16 MB, [bh][j][d]
__device__ __half g_VTh[(size_t)BHN * DIMN * KVROWS];  // 16 MB, [bh][d][j]
__device__ __half g_PTh[(size_t)LSPAN * DIMN];         // 128 KB, [l][d]

// -------- smem byte offsets (K/PT double, V TRIPLE, W/posS single) --------
#define QS_B 0                      // Q  [64][72h]        =  9216
#define KS_B 9216                   // K  2x [192][72h]    = 55296
#define VT_B 64512                  // V^T 3x [64][200h]   = 76800
#define PT_B 141312                 // P^T 2x [128][72h]   = 36864
#define WS_B 178176                 // W  [64][200h]       = 25600
#define PS_B 203776                 // posS [64][148] f16  = 18944 (group-rel skewed)
#define RS_B 222720                 // rowsums [64] f32    =   256
#define SMEM_BYTES 222976

// buffer sizes in bytes
#define KSZB 27648
#define VSZB 25600
#define PSZB 18432

// -------- strides --------
#define QROWB 144     // Q/K/PT row stride bytes (72 halves)
#define WROWB 400     // W/VT row stride bytes (200 halves)
#define PSW 148       // posS HALF stride (row = 296B; half2 reads at even cols)

#define LOG2E_F 1.4426950408889634f

__device__ __forceinline__ uint32_t smem_u32(const void* p) {
    uint32_t a;
    asm("{ .reg .u64 t; cvta.to.shared.u64 t, %1; cvt.u32.u64 %0, t; }" : "=r"(a) : "l"(p));
    return a;
}
__device__ __forceinline__ void cp16(uint32_t dst, const void* src) {
    asm volatile("cp.async.ca.shared.global [%0], [%1], 16;" :: "r"(dst), "l"(src) : "memory");
}
#define CP_COMMIT() asm volatile("cp.async.commit_group;" ::: "memory")
#define CP_WAIT0()  asm volatile("cp.async.wait_group 0;" ::: "memory")
#define CP_WAIT1()  asm volatile("cp.async.wait_group 1;" ::: "memory")
#define BAR_GRP(id) asm volatile("bar.sync %0, 128;" :: "r"(id) : "memory")

__device__ __forceinline__ void ldsm4(uint32_t r[4], uint32_t a) {
    asm volatile("ldmatrix.sync.aligned.m8n8.x4.shared.b16 {%0,%1,%2,%3}, [%4];"
        : "=r"(r[0]), "=r"(r[1]), "=r"(r[2]), "=r"(r[3]) : "r"(a));
}
__device__ __forceinline__ void ldsm2(uint32_t r[2], uint32_t a) {
    asm volatile("ldmatrix.sync.aligned.m8n8.x2.shared.b16 {%0,%1}, [%2];"
        : "=r"(r[0]), "=r"(r[1]) : "r"(a));
}
__device__ __forceinline__ void stsm2(uint32_t a, uint32_t r0, uint32_t r1) {
    asm volatile("stmatrix.sync.aligned.m8n8.x2.shared.b16 [%0], {%1,%2};"
        :: "r"(a), "r"(r0), "r"(r1) : "memory");
}
__device__ __forceinline__ void mma_f16_f32(float c[4], const uint32_t a[4], const uint32_t b[2]) {
    asm volatile(
        "mma.sync.aligned.m16n8k16.row.col.f32.f16.f16.f32 "
        "{%0,%1,%2,%3}, {%4,%5,%6,%7}, {%8,%9}, {%0,%1,%2,%3};"
        : "+f"(c[0]), "+f"(c[1]), "+f"(c[2]), "+f"(c[3])
        : "r"(a[0]), "r"(a[1]), "r"(a[2]), "r"(a[3]), "r"(b[0]), "r"(b[1]));
}

// ============ merged pre-pass: f32 -> f16 (rna), Q x0.125, V/P transposed ============
__global__ void prep_all(const float* __restrict__ Q, const float* __restrict__ K,
                         const float* __restrict__ V, const float* __restrict__ P) {
    const int x = blockIdx.x, bh = blockIdx.y, tid = threadIdx.x;
    if (x < 16) {
        size_t base = ((size_t)bh * MSEQ + x * 64) * DIMN;
        #pragma unroll
        for (int p = 0; p < 4; p++) {
            int idx = p * 256 + tid;
            float4 v = *(const float4*)(Q + base + (size_t)idx * 4);
            __half2 h0 = __floats2half2_rn(v.x * 0.125f, v.y * 0.125f);
            __half2 h1 = __floats2half2_rn(v.z * 0.125f, v.w * 0.125f);
            *(uint2*)(&g_Qh[base + (size_t)idx * 4]) =
                make_uint2(*(uint32_t*)&h0, *(uint32_t*)&h1);
        }
    } else if (x < 48) {
        size_t base = ((size_t)bh * KVROWS + (x - 16) * 64) * DIMN;
        #pragma unroll
        for (int p = 0; p < 4; p++) {
            int idx = p * 256 + tid;
            float4 v = *(const float4*)(K + base + (size_t)idx * 4);
            __half2 h0 = __floats2half2_rn(v.x, v.y);
            __half2 h1 = __floats2half2_rn(v.z, v.w);
            *(uint2*)(&g_Kh[base + (size_t)idx * 4]) =
                make_uint2(*(uint32_t*)&h0, *(uint32_t*)&h1);
        }
    } else if (x < 80) {
        __shared__ float ts[64][65];   // [j][d]
        const int j0 = (x - 48) * 64;
        size_t base = ((size_t)bh * KVROWS + j0) * DIMN;
        #pragma unroll
        for (int p = 0; p < 16; p++) {
            int idx = p * 256 + tid;
            ts[idx >> 6][idx & 63] = V[base + idx];
        }
        __syncthreads();
        const int d = tid >> 2, jq = (tid & 3) * 16;
        uint32_t u[8];
        #pragma unroll
        for (int q = 0; q < 8; q++) {
            __half2 h = __floats2half2_rn(ts[jq + 2 * q][d], ts[jq + 2 * q + 1][d]);
            u[q] = *(uint32_t*)&h;
        }
        __half* dst = &g_VTh[((size_t)bh * DIMN + d) * KVROWS + j0 + jq];
        *(uint4*)dst       = make_uint4(u[0], u[1], u[2], u[3]);
        *(uint4*)(dst + 8) = make_uint4(u[4], u[5], u[6], u[7]);
    } else {
        if (bh != 0) return;
        __shared__ float ts[64][65];   // [l][d]
        const int l0 = (x - 80) * 64;
        #pragma unroll
        for (int p = 0; p < 16; p++) {
            int idx = p * 256 + tid;
            int d = idx >> 6, lq = idx & 63;
            ts[lq][d] = P[(size_t)d * LSPAN + l0 + lq];
        }
        __syncthreads();
        const int lq = tid >> 2, dq = (tid & 3) * 16;
        uint32_t u[8];
        #pragma unroll
        for (int q = 0; q < 8; q++) {
            __half2 h = __floats2half2_rn(ts[lq][dq + 2 * q], ts[lq][dq + 2 * q + 1]);
            u[q] = *(uint32_t*)&h;
        }
        __half* dst = &g_PTh[(size_t)(l0 + lq) * DIMN + dq];
        *(uint4*)dst       = make_uint4(u[0], u[1], u[2], u[3]);
        *(uint4*)(dst + 8) = make_uint4(u[4], u[5], u[6], u[7]);
    }
}

// ==== main kernel: 1 global sync + 1 named barrier per tile, PV-then-S burst ====
__global__ void __launch_bounds__(NTHR, 1) seqattn_f16_kernel(float* __restrict__ O) {
    extern __shared__ char sm[];
    const uint32_t sb = smem_u32(sm);

    __half* psfh = (__half*)(sm + PS_B);
    float*  Rs   = (float*)(sm + RS_B);

    const int tid  = threadIdx.x;
    const int w    = tid >> 5;
    const int lane = tid & 31;
    const int g    = lane >> 2;
    const int tig  = lane & 3;

    // 16 warps = 4 m-groups x 4 n-warps
    const int wm = w >> 2;
    const int wn = w & 3;
    // content window: 18 blocks of 8 cols; wn gets {5,5,4,4}
    const int nstart = (wn < 2) ? wn * 5 : 10 + (wn - 2) * 4;
    const int ncnt   = (wn < 2) ? 5 : 4;
    const int barid  = wm + 1;

    // LDSM lane addressing helpers
    const int lr = lane & 15;
    const int lk = lane >> 4;
    const int q4 = lane >> 3;
    const int rr = lane & 7;

    const int bh = blockIdx.y;
    const int m0 = blockIdx.x * BM;

    const __half* Qh  = g_Qh  + ((size_t)bh * MSEQ + m0) * DIMN;
    const __half* Kh  = g_Kh  + (size_t)bh * KVROWS * DIMN;
    const __half* VTh = g_VTh + (size_t)bh * DIMN * KVROWS;

    // ---- prologue: one group {Q, K(0), PT(0), V(0)} ----
    {
        int r = tid >> 3, c = tid & 7;
        cp16(sb + QS_B + (uint32_t)(r * 72 + c * 8) * 2u, Qh + (size_t)r * DIMN + c * 8);
        #pragma unroll
        for (int p = 0; p < 3; p++) {
            int idx = p * NTHR + tid;
            int kr = idx >> 3, kc = idx & 7;
            cp16(sb + KS_B + (uint32_t)(kr * 72 + kc * 8) * 2u,
                 Kh + (size_t)(m0 + kr) * DIMN + kc * 8);
        }
        #pragma unroll
        for (int p = 0; p < 2; p++) {
            int idx = p * NTHR + tid;
            int pr = idx >> 3, pc = idx & 7;
            cp16(sb + PT_B + (uint32_t)(pr * 72 + pc * 8) * 2u,
                 g_PTh + (size_t)pr * DIMN + pc * 8);
        }
        #pragma unroll
        for (int p = 0; p < 3; p++) {
            int idx = p * NTHR + tid;
            int d = idx / 24, c24 = idx % 24;
            cp16(sb + VT_B + (uint32_t)(d * 200 + c24 * 8) * 2u,
                 VTh + (size_t)d * KVROWS + m0 + c24 * 8);
        }
        CP_COMMIT();
    }
    if (tid < 64) Rs[tid] = 0.f;

    // lane-constant fragment base addresses
    const uint32_t aQbase = sb + QS_B + (uint32_t)((wm * 16 + lr) * QROWB + lk * 16);
    const uint32_t aWbase = sb + WS_B + (uint32_t)((wm * 16 + lr) * WROWB + lk * 16);
    const uint32_t sWbase = sb + WS_B + (uint32_t)((wm * 16 + lr) * WROWB);
    const uint32_t bRow  = (uint32_t)(((q4 >> 1) * 8 + rr) * QROWB + (q4 & 1) * 16);
    const uint32_t vRow  = (uint32_t)(((q4 >> 1) * 8 + rr) * WROWB + (q4 & 1) * 16);
    const uint32_t bRow2 = (uint32_t)(rr * QROWB + ((lane >> 3) & 1) * 16);

    CP_WAIT0();
    __syncthreads();

    // ---- hoist Q fragments (tile-invariant) ----
    uint32_t aq[4][4];
    #pragma unroll
    for (int ks = 0; ks < 4; ks++) ldsm4(aq[ks], aQbase + ks * 32);

    float cO[2][4];
    #pragma unroll
    for (int b = 0; b < 2; b++)
        #pragma unroll
        for (int c = 0; c < 4; c++) cO[b][c] = 0.f;
    float rsv[2] = {0.f, 0.f};

    // V(t) lives in vbuf[t % 3]
    // ===== loop: iter t = PV(t-1) + S(t) burst, posS, BAR, exp, STSM W(t) =====
    for (int t = 0; t <= NT; t++) {
        const uint32_t ksOff = sb + KS_B + (uint32_t)(t & 1) * KSZB;
        const uint32_t ptOff = sb + PT_B + (uint32_t)(t & 1) * PSZB;
        const uint32_t vtOff = sb + VT_B + (uint32_t)((t + 2) % 3) * VSZB;  // V(t-1)

        if (t > 0) __syncthreads();   // retires K(t-1)/W(t-1)/posS(t-1)/V(t-2) reads

        // issue {K(t+1), PT(t+1), V(t+1)} in one group
        if (t + 1 < NT) {
            const int jg0n = m0 + (t + 1) * BL;
            const uint32_t kdst = sb + KS_B + (uint32_t)((t + 1) & 1) * KSZB;
            const uint32_t pdst = sb + PT_B + (uint32_t)((t + 1) & 1) * PSZB;
            const uint32_t vdst = sb + VT_B + (uint32_t)((t + 1) % 3) * VSZB;
            #pragma unroll
            for (int p = 0; p < 3; p++) {
                int idx = p * NTHR + tid;
                int kr = idx >> 3, kc = idx & 7;
                cp16(kdst + (uint32_t)(kr * 72 + kc * 8) * 2u,
                     Kh + (size_t)(jg0n + kr) * DIMN + kc * 8);
            }
            #pragma unroll
            for (int p = 0; p < 2; p++) {
                int idx = p * NTHR + tid;
                int pr = idx >> 3, pc = idx & 7;
                cp16(pdst + (uint32_t)(pr * 72 + pc * 8) * 2u,
                     g_PTh + (size_t)((t + 1) * BL + pr) * DIMN + pc * 8);
            }
            #pragma unroll
            for (int p = 0; p < 3; p++) {
                int idx = p * NTHR + tid;
                int d = idx / 24, c24 = idx % 24;
                cp16(vdst + (uint32_t)(d * 200 + c24 * 8) * 2u,
                     VTh + (size_t)d * KVROWS + jg0n + c24 * 8);
            }
        }
        CP_COMMIT();
        CP_WAIT1();   // all groups except newest done: K(t),PT(t),V(t),V(t-1) resident

        // ===== PV(t-1): independent of this tile's S/exp — issue first =====
        if (t > 0) {
            #pragma unroll
            for (int kk = 0; kk < 9; kk++) {
                uint32_t a[4];
                ldsm4(a, aWbase + kk * 32);
                uint32_t bv[4];
                ldsm4(bv, vtOff + (uint32_t)(wn * 16 * WROWB) + vRow + (uint32_t)(wm * 32 + kk * 32));
                mma_f16_f32(cO[0], a, bv);
                mma_f16_f32(cO[1], a, bv + 2);
            }
        }

        float cC[5][4], cP[4][4];
        uint32_t hw2s[5][2];

        if (t < NT) {
            // ===== S GEMM: content (144-window) + pos, f32 acc =====
            #pragma unroll
            for (int nb = 0; nb < 5; nb++)
                #pragma unroll
                for (int c = 0; c < 4; c++) cC[nb][c] = 0.f;
            #pragma unroll
            for (int nb = 0; nb < 4; nb++)
                #pragma unroll
                for (int c = 0; c < 4; c++) cP[nb][c] = 0.f;

            #pragma unroll
            for (int ks = 0; ks < 4; ks++) {
                #pragma unroll
                for (int pp = 0; pp < 2; pp++) {      // pos: 2 x4 = 4 blocks
                    uint32_t bb[4];
                    ldsm4(bb, ptOff + (uint32_t)((wn * 32 + pp * 16) * QROWB) + bRow + ks * 32);
                    mma_f16_f32(cP[pp * 2],     aq[ks], bb);
                    mma_f16_f32(cP[pp * 2 + 1], aq[ks], bb + 2);
                }
                #pragma unroll
                for (int pp = 0; pp < 2; pp++) {      // content: 2 x4 = 4 blocks
                    uint32_t bb[4];
                    ldsm4(bb, ksOff + (uint32_t)((wm * 16 + (nstart + pp * 2) * 8) * QROWB) + bRow + ks * 32);
                    mma_f16_f32(cC[pp * 2],     aq[ks], bb);
                    mma_f16_f32(cC[pp * 2 + 1], aq[ks], bb + 2);
                }
                if (wn < 2) {                          // 5th content block (x2)
                    uint32_t b2[2];
                    ldsm2(b2, ksOff + (uint32_t)((wm * 16 + (nstart + 4) * 8) * QROWB) + bRow2 + ks * 32);
                    mma_f16_f32(cC[4], aq[ks], b2);
                }
            }

            // ---- pos x log2e -> posS f16, skewed group-relative cols ----
            // slot(i, l) = psfh[i*PSW + (ig + l)]; reader col (even) = ig + l.
            #pragma unroll
            for (int nb = 0; nb < 4; nb++) {
                int lp = wn * 32 + nb * 8 + 2 * tig;
                int i1 = wm * 16 + g;          // ig = g
                int i2 = i1 + 8;               // ig = g + 8
                psfh[i1 * PSW + (g + lp)]         = __float2half_rn(cP[nb][0] * LOG2E_F);
                psfh[i1 * PSW + (g + lp + 1)]     = __float2half_rn(cP[nb][1] * LOG2E_F);
                psfh[i2 * PSW + (g + 8 + lp)]     = __float2half_rn(cP[nb][2] * LOG2E_F);
                psfh[i2 * PSW + (g + 8 + lp + 1)] = __float2half_rn(cP[nb][3] * LOG2E_F);
            }
        }
        BAR_GRP(barid);   // group: PV(t-1) done reading W; posS(t) visible

        if (t < NT) {
            // ---- exp(t): posS reads are aligned half2 ----
            #pragma unroll
            for (int nb = 0; nb < 5; nb++) {
                if (nb < ncnt) {
                    int colrel = (nstart + nb) * 8 + 2 * tig;   // even
                    #pragma unroll
                    for (int h = 0; h < 2; h++) {
                        int ig = g + 8 * h;
                        int i  = wm * 16 + ig;
                        float2 pv = __half22float2(*(const __half2*)(psfh + i * PSW + colrel));
                        float s0 = cC[nb][2 * h], s1 = cC[nb][2 * h + 1];
                        int l0 = colrel - ig;
                        float w0 = 0.f, w1 = 0.f;
                        if (l0 >= 0 && l0 < 128)
                            w0 = exp2f(fmaf(s0, LOG2E_F, pv.x));
                        if (l0 + 1 >= 0 && l0 + 1 < 128)
                            w1 = exp2f(fmaf(s1, LOG2E_F, pv.y));
                        __half2 hw = __floats2half2_rn(w0, w1);
                        float2 bk = __half22float2(hw);
                        rsv[h] += bk.x + bk.y;
                        hw2s[nb][h] = *(uint32_t*)&hw;
                    }
                }
            }
            // ---- STSM W(t) (group PV already retired at BAR above) ----
            #pragma unroll
            for (int nb = 0; nb < 5; nb++) {
                if (nb < ncnt)
                    stsm2(sWbase + (uint32_t)((nstart + nb) * 16), hw2s[nb][0], hw2s[nb][1]);
            }
        }
    }

    // ---- rowsum reduction (cross-wn) ----
    __syncthreads();
    #pragma unroll
    for (int h = 0; h < 2; h++) {
        float v = rsv[h];
        v += __shfl_xor_sync(0xffffffffu, v, 1);
        v += __shfl_xor_sync(0xffffffffu, v, 2);
        if (tig == 0) {
            int i = wm * 16 + g + 8 * h;
            atomicAdd(&Rs[i], v);
        }
    }
    __syncthreads();

    // ---- normalize + store (warp owns rows wm*16.., cols wn*16..) ----
    {
        int i1 = wm * 16 + g;
        float inv0 = 1.f / Rs[i1];
        float inv1 = 1.f / Rs[i1 + 8];
        #pragma unroll
        for (int nb = 0; nb < 2; nb++) {
            int d = wn * 16 + nb * 8 + 2 * tig;
            float2 o0 = make_float2(cO[nb][0] * inv0, cO[nb][1] * inv0);
            float2 o1 = make_float2(cO[nb][2] * inv1, cO[nb][3] * inv1);
            *(float2*)(O + ((size_t)bh * MSEQ + m0 + i1) * DIMN + d)     = o0;
            *(float2*)(O + ((size_t)bh * MSEQ + m0 + i1 + 8) * DIMN + d) = o1;
        }
    }
}

extern "C" void kernel_launch(void* const* d_in, const int* in_sizes, int n_in,
                              void* d_out, int out_size) {
    const float* Q = (const float*)d_in[0];
    const float* K = (const float*)d_in[1];
    const float* V = (const float*)d_in[2];
    const float* P = (const float*)d_in[3];
    float* O = (float*)d_out;
    (void)n_in; (void)in_sizes; (void)out_size;

    prep_all<<<dim3(96, BHN), 256>>>(Q, K, V, P);

    cudaFuncSetAttribute(seqattn_f16_kernel,
                         cudaFuncAttributeMaxDynamicSharedMemorySize, SMEM_BYTES);
    dim3 grid(MSEQ / BM, BHN);   // (16, 64)
    seqattn_f16_kernel<<<grid, NTHR, SMEM_BYTES>>>(O);
}